// round 13
// baseline (speedup 1.0000x reference)
#include <cuda_runtime.h>
#include <cuda_bf16.h>

// ---------------------------------------------------------------------------
// NDCG loss, N = 2^24.  Two kernels:
// k_count: branch-free batched float4 loads (true MLP=8) -> ballot bitmask +
//          block counts; LAST block (ticket) scans counts -> g_pre[], total P.
// k_main:  batched float4 predict loads + MUFU (LG2/RCP) terms -> g_partial;
//          LAST block (ticket) does fixed-order double reduce -> out[0].
// Mask layout: per 128-element tile, words w0..w3; w_d bit t = elem 4t+d.
// ---------------------------------------------------------------------------

#define CHUNK    8192
#define NTHREADS 256
#define NWARPS   (NTHREADS / 32)
#define MAX_TILES  (1 << 18)   // n up to 2^25
#define MAX_BLOCKS 8192

__device__ uint4    g_mask4[MAX_TILES];
__device__ int      g_bcnt[MAX_BLOCKS];
__device__ int      g_pre[MAX_BLOCKS + 1];   // exclusive prefix; g_pre[nb] = P
__device__ float    g_partial[MAX_BLOCKS];
__device__ unsigned g_cnt1 = 0;              // ticket counters (self-reset)
__device__ unsigned g_cnt2 = 0;

// ---------------------------------------------------------------------------
__global__ __launch_bounds__(NTHREADS)
void k_count(const float* __restrict__ score, int n, int nb) {
    int tid  = threadIdx.x;
    int lane = tid & 31;
    int warp = tid >> 5;
    int b    = blockIdx.x;
    int blockBase = b * CHUNK;
    int warpBase  = blockBase + warp * 1024;   // 8 tiles of 128

    // ---- loads: uniform branch hoisted -> clean path is 8 straight LDG.128 ----
    float4 v[8];
    if (blockBase + CHUNK <= n) {
#pragma unroll
        for (int j = 0; j < 8; ++j)
            v[j] = *reinterpret_cast<const float4*>(score + warpBase + j * 128 + lane * 4);
    } else {
#pragma unroll
        for (int j = 0; j < 8; ++j) {
            int myIdx = warpBase + j * 128 + lane * 4;
            v[j].x = (myIdx + 0 < n) ? score[myIdx + 0] : 0.0f;
            v[j].y = (myIdx + 1 < n) ? score[myIdx + 1] : 0.0f;
            v[j].z = (myIdx + 2 < n) ? score[myIdx + 2] : 0.0f;
            v[j].w = (myIdx + 3 < n) ? score[myIdx + 3] : 0.0f;
        }
    }

    // ---- ballots + mask stores + count ----
    int cnt = 0;
#pragma unroll
    for (int j = 0; j < 8; ++j) {
        unsigned w0 = __ballot_sync(0xffffffffu, v[j].x > 0.0f);
        unsigned w1 = __ballot_sync(0xffffffffu, v[j].y > 0.0f);
        unsigned w2 = __ballot_sync(0xffffffffu, v[j].z > 0.0f);
        unsigned w3 = __ballot_sync(0xffffffffu, v[j].w > 0.0f);
        if (lane == 0) g_mask4[(warpBase + j * 128) >> 7] = make_uint4(w0, w1, w2, w3);
        cnt += __popc(w0) + __popc(w1) + __popc(w2) + __popc(w3);
    }
    __shared__ int wc[NWARPS];
    if (lane == 0) wc[warp] = cnt;
    __syncthreads();

    __shared__ unsigned s_ticket;
    if (tid == 0) {
        int s = 0;
#pragma unroll
        for (int i = 0; i < NWARPS; ++i) s += wc[i];
        g_bcnt[b] = s;
        __threadfence();                       // publish before ticket
        s_ticket = atomicAdd(&g_cnt1, 1u);
    }
    __syncthreads();

    // ---- last block: exclusive scan of g_bcnt -> g_pre ----
    if (s_ticket == (unsigned)(nb - 1)) {
        __threadfence();                       // acquire all g_bcnt
        int L  = (nb + NTHREADS - 1) / NTHREADS;   // <= 32
        int s0 = tid * L;
        int local[32];
        int sum = 0;
        for (int i = 0; i < L; ++i) {
            int idx = s0 + i;
            int c = (idx < nb) ? g_bcnt[idx] : 0;
            local[i] = sum;                    // exclusive within segment
            sum += c;
        }
        int inc = sum;
#pragma unroll
        for (int o = 1; o < 32; o <<= 1) {
            int t = __shfl_up_sync(0xffffffffu, inc, o);
            if (lane >= o) inc += t;
        }
        __shared__ int ws[NWARPS];
        if (lane == 31) ws[warp] = inc;
        __syncthreads();
        if (tid == 0) {
            int r = 0;
#pragma unroll
            for (int i = 0; i < NWARPS; ++i) { int t = ws[i]; ws[i] = r; r += t; }
        }
        __syncthreads();
        int excl = ws[warp] + (inc - sum);
        for (int i = 0; i < L; ++i) {
            int idx = s0 + i;
            if (idx < nb) g_pre[idx] = excl + local[i];
        }
        if (tid == NTHREADS - 1) g_pre[nb] = excl + sum;   // total P
        if (tid == 0) g_cnt1 = 0;              // reset for next graph replay
    }
}

// ---------------------------------------------------------------------------
// pos: (p/(k+1) - s/log2(k+1))^2 via num=p*l - s*(k+1), den=(k+1)*l.
// neg: (p/(P+m+1))^2, m = idx+1-kinc.  MUFU: 1 LG2 + 1 RCP; one I2F.
__device__ __forceinline__ float term(float praw, int kinc, int pos, int idx,
                                      float inv_sum_s, float s_val, int P) {
    float p  = praw * inv_sum_s;
    int   di = pos ? (kinc + 1) : (P + idx + 2 - kinc);
    float fd = (float)di;
    float l  = __log2f(fd);
    float num = pos ? fmaf(-s_val, fd, p * l) : p;
    float den = pos ? fd * l : fd;
    return __fdividef(num, den);
}

__global__ __launch_bounds__(NTHREADS)
void k_main(const float* __restrict__ predict, float* __restrict__ out,
            int n, int nb) {
    int tid  = threadIdx.x;
    int lane = tid & 31;
    int warp = tid >> 5;
    int b    = blockIdx.x;

    const int P    = g_pre[nb];
    int kbase      = g_pre[b];
    const float fS        = (float)P;        // S == P exactly (0/1 scores)
    const float s_val     = 1.0f / fS;
    const float sum_s     = fS * s_val;      // ~= jnp.sum(s)
    const float inv_sum_s = 1.0f / sum_s;

    // ---- warp's 32 mask words + per-warp k offsets ----
    int blockBase = b * CHUNK;
    int warpBase  = blockBase + warp * 1024;
    const unsigned* g_words = reinterpret_cast<const unsigned*>(g_mask4);
    unsigned myword = g_words[(blockBase >> 5) + warp * 32 + lane];
    int wtot = __popc(myword);
#pragma unroll
    for (int o = 16; o; o >>= 1) wtot += __shfl_xor_sync(0xffffffffu, wtot, o);
    __shared__ int s_wc[NWARPS];
    if (lane == 0) s_wc[warp] = wtot;
    __syncthreads();
#pragma unroll
    for (int i = 0; i < NWARPS; ++i)
        if (i < warp) kbase += s_wc[i];

    // ---- predict loads: uniform branch hoisted (8 straight LDG.128) ----
    float4 pv[8];
    if (blockBase + CHUNK <= n) {
#pragma unroll
        for (int j = 0; j < 8; ++j)
            pv[j] = *reinterpret_cast<const float4*>(predict + warpBase + j * 128 + lane * 4);
    } else {
#pragma unroll
        for (int j = 0; j < 8; ++j) {
            int myIdx = warpBase + j * 128 + lane * 4;
            pv[j].x = (myIdx + 0 < n) ? predict[myIdx + 0] : 0.0f;
            pv[j].y = (myIdx + 1 < n) ? predict[myIdx + 1] : 0.0f;
            pv[j].z = (myIdx + 2 < n) ? predict[myIdx + 2] : 0.0f;
            pv[j].w = (myIdx + 3 < n) ? predict[myIdx + 3] : 0.0f;
        }
    }

    // ---- terms ----
    const unsigned lt = (1u << lane) - 1u;
    float acc = 0.0f;
#pragma unroll
    for (int j = 0; j < 8; ++j) {
        unsigned w0 = __shfl_sync(0xffffffffu, myword, 4 * j + 0);
        unsigned w1 = __shfl_sync(0xffffffffu, myword, 4 * j + 1);
        unsigned w2 = __shfl_sync(0xffffffffu, myword, 4 * j + 2);
        unsigned w3 = __shfl_sync(0xffffffffu, myword, 4 * j + 3);
        int myIdx = warpBase + j * 128 + lane * 4;
        int pre4 = __popc(w0 & lt) + __popc(w1 & lt)
                 + __popc(w2 & lt) + __popc(w3 & lt);
        int b0 = (w0 >> lane) & 1;
        int b1 = (w1 >> lane) & 1;
        int b2 = (w2 >> lane) & 1;
        int b3 = (w3 >> lane) & 1;
        int k0 = kbase + pre4 + b0;
        int k1 = k0 + b1;
        int k2 = k1 + b2;
        int k3 = k2 + b3;
        float t0 = term(pv[j].x, k0, b0, myIdx + 0, inv_sum_s, s_val, P);
        float t1 = term(pv[j].y, k1, b1, myIdx + 1, inv_sum_s, s_val, P);
        float t2 = term(pv[j].z, k2, b2, myIdx + 2, inv_sum_s, s_val, P);
        float t3 = term(pv[j].w, k3, b3, myIdx + 3, inv_sum_s, s_val, P);
        acc = fmaf(t0, t0, acc);
        acc = fmaf(t1, t1, acc);
        acc = fmaf(t2, t2, acc);
        acc = fmaf(t3, t3, acc);
        kbase += __popc(w0) + __popc(w1) + __popc(w2) + __popc(w3);
    }

    // ---- block reduce -> g_partial ----
#pragma unroll
    for (int o = 16; o; o >>= 1) acc += __shfl_xor_sync(0xffffffffu, acc, o);
    __shared__ float s_acc[NWARPS];
    if (lane == 0) s_acc[warp] = acc;
    __syncthreads();

    __shared__ unsigned s_ticket;
    if (tid == 0) {
        float s = 0.0f;
#pragma unroll
        for (int i = 0; i < NWARPS; ++i) s += s_acc[i];
        g_partial[b] = s;
        __threadfence();
        s_ticket = atomicAdd(&g_cnt2, 1u);
    }
    __syncthreads();

    // ---- last block: fixed-order double reduce -> out[0] ----
    if (s_ticket == (unsigned)(nb - 1)) {
        __threadfence();
        double s = 0.0;
        for (int i = tid; i < nb; i += NTHREADS) s += (double)g_partial[i];
#pragma unroll
        for (int o = 16; o; o >>= 1) s += __shfl_down_sync(0xffffffffu, s, o);
        __shared__ double sd[NWARPS];
        if (lane == 0) sd[warp] = s;
        __syncthreads();
        if (tid == 0) {
            double t = 0.0;
#pragma unroll
            for (int i = 0; i < NWARPS; ++i) t += sd[i];
            out[0] = (float)t;
            g_cnt2 = 0;                        // reset for next graph replay
        }
    }
}

extern "C" void kernel_launch(void* const* d_in, const int* in_sizes, int n_in,
                              void* d_out, int out_size) {
    const float* predict = (const float*)d_in[0];
    const float* score   = (const float*)d_in[1];
    int n  = in_sizes[0];
    int nb = (n + CHUNK - 1) / CHUNK;
    if (nb > MAX_BLOCKS) nb = MAX_BLOCKS;  // (n fixed at 2^24 -> nb = 2048)

    k_count<<<nb, NTHREADS>>>(score, n, nb);
    k_main <<<nb, NTHREADS>>>(predict, (float*)d_out, n, nb);
}

// round 15
// speedup vs baseline: 1.0442x; 1.0442x over previous
#include <cuda_runtime.h>
#include <cuda_bf16.h>

// ---------------------------------------------------------------------------
// NDCG loss, N = 2^24.  Two kernels, MLP=2 pair-batched streaming.
// k_count: score -> ballot bitmask + block counts; last block scans -> g_pre.
// k_main:  predict + mask -> sum of u^2 terms; last block: *inv^2 -> out[0].
// Mask layout: per 128-element tile, words w0..w3; w_d bit t = elem 4t+d.
// loss = inv_sum_s^2 * sum(u^2):
//   pos u = (praw*l - s2*(k+1)) / ((k+1)*l),  l = log2(k+1), s2 = s*sum_s
//   neg u = praw / (P+m+1)
// ---------------------------------------------------------------------------

#define CHUNK    8192
#define NTHREADS 256
#define NWARPS   (NTHREADS / 32)
#define MAX_TILES  (1 << 18)
#define MAX_BLOCKS 8192

__device__ uint4    g_mask4[MAX_TILES];
__device__ int      g_bcnt[MAX_BLOCKS];
__device__ int      g_pre[MAX_BLOCKS + 1];   // exclusive prefix; g_pre[nb] = P
__device__ float    g_partial[MAX_BLOCKS];
__device__ unsigned g_cnt1 = 0;              // ticket counters (self-reset)
__device__ unsigned g_cnt2 = 0;

// ---------------------------------------------------------------------------
__global__ __launch_bounds__(NTHREADS)
void k_count(const float* __restrict__ score, int n, int nb) {
    int tid  = threadIdx.x;
    int lane = tid & 31;
    int warp = tid >> 5;
    int b    = blockIdx.x;
    int blockBase = b * CHUNK;
    int warpBase  = blockBase + warp * 1024;   // 8 tiles of 128
    bool full = (blockBase + CHUNK <= n);

    int cnt = 0;
#pragma unroll 1
    for (int jj = 0; jj < 4; ++jj) {           // 2 tiles per iter -> MLP=2
        int t0 = warpBase + (2 * jj) * 128;
        int t1 = t0 + 128;
        float4 a, c;
        if (full) {
            a = *reinterpret_cast<const float4*>(score + t0 + lane * 4);
            c = *reinterpret_cast<const float4*>(score + t1 + lane * 4);
        } else {
            int i0 = t0 + lane * 4, i1 = t1 + lane * 4;
            a.x = (i0 + 0 < n) ? score[i0 + 0] : 0.0f;
            a.y = (i0 + 1 < n) ? score[i0 + 1] : 0.0f;
            a.z = (i0 + 2 < n) ? score[i0 + 2] : 0.0f;
            a.w = (i0 + 3 < n) ? score[i0 + 3] : 0.0f;
            c.x = (i1 + 0 < n) ? score[i1 + 0] : 0.0f;
            c.y = (i1 + 1 < n) ? score[i1 + 1] : 0.0f;
            c.z = (i1 + 2 < n) ? score[i1 + 2] : 0.0f;
            c.w = (i1 + 3 < n) ? score[i1 + 3] : 0.0f;
        }
        unsigned a0 = __ballot_sync(0xffffffffu, a.x > 0.0f);
        unsigned a1 = __ballot_sync(0xffffffffu, a.y > 0.0f);
        unsigned a2 = __ballot_sync(0xffffffffu, a.z > 0.0f);
        unsigned a3 = __ballot_sync(0xffffffffu, a.w > 0.0f);
        if (lane == 0) g_mask4[t0 >> 7] = make_uint4(a0, a1, a2, a3);
        cnt += __popc(a0) + __popc(a1) + __popc(a2) + __popc(a3);
        unsigned c0 = __ballot_sync(0xffffffffu, c.x > 0.0f);
        unsigned c1 = __ballot_sync(0xffffffffu, c.y > 0.0f);
        unsigned c2 = __ballot_sync(0xffffffffu, c.z > 0.0f);
        unsigned c3 = __ballot_sync(0xffffffffu, c.w > 0.0f);
        if (lane == 0) g_mask4[t1 >> 7] = make_uint4(c0, c1, c2, c3);
        cnt += __popc(c0) + __popc(c1) + __popc(c2) + __popc(c3);
    }
    __shared__ int wc[NWARPS];
    if (lane == 0) wc[warp] = cnt;
    __syncthreads();

    __shared__ unsigned s_ticket;
    if (tid == 0) {
        int s = 0;
#pragma unroll
        for (int i = 0; i < NWARPS; ++i) s += wc[i];
        g_bcnt[b] = s;
        __threadfence();
        s_ticket = atomicAdd(&g_cnt1, 1u);
    }
    __syncthreads();

    // ---- last block: exclusive scan of g_bcnt -> g_pre ----
    if (s_ticket == (unsigned)(nb - 1)) {
        __threadfence();
        int L  = (nb + NTHREADS - 1) / NTHREADS;   // <= 32
        int s0 = tid * L;
        int local[32];
        int sum = 0;
        for (int i = 0; i < L; ++i) {
            int idx = s0 + i;
            int c = (idx < nb) ? g_bcnt[idx] : 0;
            local[i] = sum;
            sum += c;
        }
        int inc = sum;
#pragma unroll
        for (int o = 1; o < 32; o <<= 1) {
            int t = __shfl_up_sync(0xffffffffu, inc, o);
            if (lane >= o) inc += t;
        }
        __shared__ int ws[NWARPS];
        if (lane == 31) ws[warp] = inc;
        __syncthreads();
        if (tid == 0) {
            int r = 0;
#pragma unroll
            for (int i = 0; i < NWARPS; ++i) { int t = ws[i]; ws[i] = r; r += t; }
        }
        __syncthreads();
        int excl = ws[warp] + (inc - sum);
        for (int i = 0; i < L; ++i) {
            int idx = s0 + i;
            if (idx < nb) g_pre[idx] = excl + local[i];
        }
        if (tid == NTHREADS - 1) g_pre[nb] = excl + sum;
        if (tid == 0) g_cnt1 = 0;
    }
}

// ---------------------------------------------------------------------------
__device__ __forceinline__ float uterm(float praw, int kinc, int pos, int idx,
                                       float s2, int P) {
    int   di = pos ? (kinc + 1) : (P + idx + 2 - kinc);
    float fd = (float)di;
    float l  = __log2f(fd);                   // MUFU.LG2
    float num = pos ? fmaf(-s2, fd, praw * l) : praw;
    float den = pos ? fd * l : fd;
    return __fdividef(num, den);              // MUFU.RCP + mul
}

__global__ __launch_bounds__(NTHREADS)
void k_main(const float* __restrict__ predict, float* __restrict__ out,
            int n, int nb) {
    int tid  = threadIdx.x;
    int lane = tid & 31;
    int warp = tid >> 5;
    int b    = blockIdx.x;

    const int P   = g_pre[nb];
    int kbase     = g_pre[b];
    const float fS    = (float)P;             // S == P exactly (0/1 scores)
    const float s_val = 1.0f / fS;
    const float sum_s = fS * s_val;           // ~= jnp.sum(s)
    const float s2    = s_val * sum_s;        // s / inv_sum_s

    // ---- warp's 32 mask words + per-warp k offsets ----
    int blockBase = b * CHUNK;
    int warpBase  = blockBase + warp * 1024;
    bool full = (blockBase + CHUNK <= n);
    const unsigned* g_words = reinterpret_cast<const unsigned*>(g_mask4);
    unsigned myword = g_words[(blockBase >> 5) + warp * 32 + lane];
    int wtot = __popc(myword);
#pragma unroll
    for (int o = 16; o; o >>= 1) wtot += __shfl_xor_sync(0xffffffffu, wtot, o);
    __shared__ int s_wc[NWARPS];
    if (lane == 0) s_wc[warp] = wtot;
    __syncthreads();
#pragma unroll
    for (int i = 0; i < NWARPS; ++i)
        if (i < warp) kbase += s_wc[i];

    const unsigned lt = (1u << lane) - 1u;
    float acc = 0.0f;
#pragma unroll 1
    for (int jj = 0; jj < 4; ++jj) {           // 2 tiles per iter -> MLP=2
        int tA = 2 * jj, tB = tA + 1;
        int iA = warpBase + tA * 128 + lane * 4;
        int iB = warpBase + tB * 128 + lane * 4;
        float4 pa, pb;
        if (full) {
            pa = *reinterpret_cast<const float4*>(predict + iA);
            pb = *reinterpret_cast<const float4*>(predict + iB);
        } else {
            pa.x = (iA + 0 < n) ? predict[iA + 0] : 0.0f;
            pa.y = (iA + 1 < n) ? predict[iA + 1] : 0.0f;
            pa.z = (iA + 2 < n) ? predict[iA + 2] : 0.0f;
            pa.w = (iA + 3 < n) ? predict[iA + 3] : 0.0f;
            pb.x = (iB + 0 < n) ? predict[iB + 0] : 0.0f;
            pb.y = (iB + 1 < n) ? predict[iB + 1] : 0.0f;
            pb.z = (iB + 2 < n) ? predict[iB + 2] : 0.0f;
            pb.w = (iB + 3 < n) ? predict[iB + 3] : 0.0f;
        }
        // ---- tile A ----
        {
            unsigned w0 = __shfl_sync(0xffffffffu, myword, 4 * tA + 0);
            unsigned w1 = __shfl_sync(0xffffffffu, myword, 4 * tA + 1);
            unsigned w2 = __shfl_sync(0xffffffffu, myword, 4 * tA + 2);
            unsigned w3 = __shfl_sync(0xffffffffu, myword, 4 * tA + 3);
            int pre4 = __popc(w0 & lt) + __popc(w1 & lt)
                     + __popc(w2 & lt) + __popc(w3 & lt);
            int b0 = (w0 >> lane) & 1;
            int b1 = (w1 >> lane) & 1;
            int b2 = (w2 >> lane) & 1;
            int b3 = (w3 >> lane) & 1;
            int k0 = kbase + pre4 + b0;
            int k1 = k0 + b1;
            int k2 = k1 + b2;
            int k3 = k2 + b3;
            float u0 = uterm(pa.x, k0, b0, iA + 0, s2, P);
            float u1 = uterm(pa.y, k1, b1, iA + 1, s2, P);
            float u2 = uterm(pa.z, k2, b2, iA + 2, s2, P);
            float u3 = uterm(pa.w, k3, b3, iA + 3, s2, P);
            acc = fmaf(u0, u0, acc);
            acc = fmaf(u1, u1, acc);
            acc = fmaf(u2, u2, acc);
            acc = fmaf(u3, u3, acc);
            kbase += __popc(w0) + __popc(w1) + __popc(w2) + __popc(w3);
        }
        // ---- tile B ----
        {
            unsigned w0 = __shfl_sync(0xffffffffu, myword, 4 * tB + 0);
            unsigned w1 = __shfl_sync(0xffffffffu, myword, 4 * tB + 1);
            unsigned w2 = __shfl_sync(0xffffffffu, myword, 4 * tB + 2);
            unsigned w3 = __shfl_sync(0xffffffffu, myword, 4 * tB + 3);
            int pre4 = __popc(w0 & lt) + __popc(w1 & lt)
                     + __popc(w2 & lt) + __popc(w3 & lt);
            int b0 = (w0 >> lane) & 1;
            int b1 = (w1 >> lane) & 1;
            int b2 = (w2 >> lane) & 1;
            int b3 = (w3 >> lane) & 1;
            int k0 = kbase + pre4 + b0;
            int k1 = k0 + b1;
            int k2 = k1 + b2;
            int k3 = k2 + b3;
            float u0 = uterm(pb.x, k0, b0, iB + 0, s2, P);
            float u1 = uterm(pb.y, k1, b1, iB + 1, s2, P);
            float u2 = uterm(pb.z, k2, b2, iB + 2, s2, P);
            float u3 = uterm(pb.w, k3, b3, iB + 3, s2, P);
            acc = fmaf(u0, u0, acc);
            acc = fmaf(u1, u1, acc);
            acc = fmaf(u2, u2, acc);
            acc = fmaf(u3, u3, acc);
            kbase += __popc(w0) + __popc(w1) + __popc(w2) + __popc(w3);
        }
    }

    // ---- block reduce -> g_partial ----
#pragma unroll
    for (int o = 16; o; o >>= 1) acc += __shfl_xor_sync(0xffffffffu, acc, o);
    __shared__ float s_acc[NWARPS];
    if (lane == 0) s_acc[warp] = acc;
    __syncthreads();

    __shared__ unsigned s_ticket;
    if (tid == 0) {
        float s = 0.0f;
#pragma unroll
        for (int i = 0; i < NWARPS; ++i) s += s_acc[i];
        g_partial[b] = s;
        __threadfence();
        s_ticket = atomicAdd(&g_cnt2, 1u);
    }
    __syncthreads();

    // ---- last block: fixed-order double reduce, scale by inv^2 -> out ----
    if (s_ticket == (unsigned)(nb - 1)) {
        __threadfence();
        double s = 0.0;
        for (int i = tid; i < nb; i += NTHREADS) s += (double)g_partial[i];
#pragma unroll
        for (int o = 16; o; o >>= 1) s += __shfl_down_sync(0xffffffffu, s, o);
        __shared__ double sd[NWARPS];
        if (lane == 0) sd[warp] = s;
        __syncthreads();
        if (tid == 0) {
            double t = 0.0;
#pragma unroll
            for (int i = 0; i < NWARPS; ++i) t += sd[i];
            float inv = 1.0f / sum_s;          // inv_sum_s
            out[0] = (float)(t * (double)(inv * inv));
            g_cnt2 = 0;
        }
    }
}

extern "C" void kernel_launch(void* const* d_in, const int* in_sizes, int n_in,
                              void* d_out, int out_size) {
    const float* predict = (const float*)d_in[0];
    const float* score   = (const float*)d_in[1];
    int n  = in_sizes[0];
    int nb = (n + CHUNK - 1) / CHUNK;
    if (nb > MAX_BLOCKS) nb = MAX_BLOCKS;

    k_count<<<nb, NTHREADS>>>(score, n, nb);
    k_main <<<nb, NTHREADS>>>(predict, (float*)d_out, n, nb);
}

// round 17
// speedup vs baseline: 1.0450x; 1.0007x over previous
#include <cuda_runtime.h>
#include <cuda_bf16.h>

// ---------------------------------------------------------------------------
// NDCG loss, N = 2^24.
// k_count: pair-batched float4 score loads -> ballot bitmask + block counts;
//          last block (ticket) scans counts -> g_pre[], total P.
// k_main:  full-unrolled, software-pipelined: per tile LDG.128 predict +
//          broadcast LDG.128 mask uint4; branchless FSEL term math with
//          incremental rank counters; last block double-reduce -> out[0].
// Mask layout: per 128-element tile, words w0..w3; w_d bit t = elem 4t+d.
// loss = inv_sum_s^2 * sum(u^2):
//   pos u = (praw*l - s2*(k+1)) / ((k+1)*l),  l = log2(k+1), s2 = s*sum_s
//   neg u = praw / (P+m+1)
// ---------------------------------------------------------------------------

#define CHUNK    8192
#define NTHREADS 256
#define NWARPS   (NTHREADS / 32)
#define MAX_TILES  (1 << 18)
#define MAX_BLOCKS 8192

__device__ uint4    g_mask4[MAX_TILES];
__device__ int      g_bcnt[MAX_BLOCKS];
__device__ int      g_pre[MAX_BLOCKS + 1];   // exclusive prefix; g_pre[nb] = P
__device__ float    g_partial[MAX_BLOCKS];
__device__ unsigned g_cnt1 = 0;              // ticket counters (self-reset)
__device__ unsigned g_cnt2 = 0;

// ---------------------------------------------------------------------------
__global__ __launch_bounds__(NTHREADS)
void k_count(const float* __restrict__ score, int n, int nb) {
    int tid  = threadIdx.x;
    int lane = tid & 31;
    int warp = tid >> 5;
    int b    = blockIdx.x;
    int blockBase = b * CHUNK;
    int warpBase  = blockBase + warp * 1024;   // 8 tiles of 128
    bool full = (blockBase + CHUNK <= n);

    int cnt = 0;
#pragma unroll 1
    for (int jj = 0; jj < 4; ++jj) {           // 2 tiles per iter -> MLP=2
        int t0 = warpBase + (2 * jj) * 128;
        int t1 = t0 + 128;
        float4 a, c;
        if (full) {
            a = *reinterpret_cast<const float4*>(score + t0 + lane * 4);
            c = *reinterpret_cast<const float4*>(score + t1 + lane * 4);
        } else {
            int i0 = t0 + lane * 4, i1 = t1 + lane * 4;
            a.x = (i0 + 0 < n) ? score[i0 + 0] : 0.0f;
            a.y = (i0 + 1 < n) ? score[i0 + 1] : 0.0f;
            a.z = (i0 + 2 < n) ? score[i0 + 2] : 0.0f;
            a.w = (i0 + 3 < n) ? score[i0 + 3] : 0.0f;
            c.x = (i1 + 0 < n) ? score[i1 + 0] : 0.0f;
            c.y = (i1 + 1 < n) ? score[i1 + 1] : 0.0f;
            c.z = (i1 + 2 < n) ? score[i1 + 2] : 0.0f;
            c.w = (i1 + 3 < n) ? score[i1 + 3] : 0.0f;
        }
        unsigned a0 = __ballot_sync(0xffffffffu, a.x > 0.0f);
        unsigned a1 = __ballot_sync(0xffffffffu, a.y > 0.0f);
        unsigned a2 = __ballot_sync(0xffffffffu, a.z > 0.0f);
        unsigned a3 = __ballot_sync(0xffffffffu, a.w > 0.0f);
        if (lane == 0) g_mask4[t0 >> 7] = make_uint4(a0, a1, a2, a3);
        cnt += __popc(a0) + __popc(a1) + __popc(a2) + __popc(a3);
        unsigned c0 = __ballot_sync(0xffffffffu, c.x > 0.0f);
        unsigned c1 = __ballot_sync(0xffffffffu, c.y > 0.0f);
        unsigned c2 = __ballot_sync(0xffffffffu, c.z > 0.0f);
        unsigned c3 = __ballot_sync(0xffffffffu, c.w > 0.0f);
        if (lane == 0) g_mask4[t1 >> 7] = make_uint4(c0, c1, c2, c3);
        cnt += __popc(c0) + __popc(c1) + __popc(c2) + __popc(c3);
    }
    __shared__ int wc[NWARPS];
    if (lane == 0) wc[warp] = cnt;
    __syncthreads();

    __shared__ unsigned s_ticket;
    if (tid == 0) {
        int s = 0;
#pragma unroll
        for (int i = 0; i < NWARPS; ++i) s += wc[i];
        g_bcnt[b] = s;
        __threadfence();
        s_ticket = atomicAdd(&g_cnt1, 1u);
    }
    __syncthreads();

    // ---- last block: exclusive scan of g_bcnt -> g_pre ----
    if (s_ticket == (unsigned)(nb - 1)) {
        __threadfence();
        int L  = (nb + NTHREADS - 1) / NTHREADS;   // <= 32
        int s0 = tid * L;
        int local[32];
        int sum = 0;
        for (int i = 0; i < L; ++i) {
            int idx = s0 + i;
            int c = (idx < nb) ? g_bcnt[idx] : 0;
            local[i] = sum;
            sum += c;
        }
        int inc = sum;
#pragma unroll
        for (int o = 1; o < 32; o <<= 1) {
            int t = __shfl_up_sync(0xffffffffu, inc, o);
            if (lane >= o) inc += t;
        }
        __shared__ int ws[NWARPS];
        if (lane == 31) ws[warp] = inc;
        __syncthreads();
        if (tid == 0) {
            int r = 0;
#pragma unroll
            for (int i = 0; i < NWARPS; ++i) { int t = ws[i]; ws[i] = r; r += t; }
        }
        __syncthreads();
        int excl = ws[warp] + (inc - sum);
        for (int i = 0; i < L; ++i) {
            int idx = s0 + i;
            if (idx < nb) g_pre[idx] = excl + local[i];
        }
        if (tid == NTHREADS - 1) g_pre[nb] = excl + sum;
        if (tid == 0) g_cnt1 = 0;
    }
}

// ---------------------------------------------------------------------------
// Branchless per-element term. b in {0,1}.
//   fd = (float)(b ? kp1 : dn);  fl = b ? log2(fd) : 1;  cs = b ? s2 : 0
//   u = (praw*fl - cs*fd) / (fd*fl)
__device__ __forceinline__ float uterm(float praw, int bint, int kp1, int dn,
                                       float s2) {
    int   di = bint ? kp1 : dn;          // ISETP+SEL (int, no fp deps)
    float fd = (float)di;                 // I2F
    float l  = __log2f(fd);               // MUFU.LG2
    float fl = bint ? l : 1.0f;           // FSEL
    float cs = bint ? s2 : 0.0f;          // FSEL
    float num = fmaf(-cs, fd, praw * fl); // FMUL+FFMA
    float den = fd * fl;                  // FMUL
    return __fdividef(num, den);          // MUFU.RCP+FMUL
}

__global__ __launch_bounds__(NTHREADS)
void k_main(const float* __restrict__ predict, float* __restrict__ out,
            int n, int nb) {
    int tid  = threadIdx.x;
    int lane = tid & 31;
    int warp = tid >> 5;
    int b    = blockIdx.x;

    const int P   = g_pre[nb];
    int kwarp     = g_pre[b];             // becomes warp's exclusive base below
    const float fS    = (float)P;         // S == P exactly (0/1 scores)
    const float s_val = 1.0f / fS;
    const float sum_s = fS * s_val;       // ~= jnp.sum(s)
    const float s2    = s_val * sum_s;

    // ---- phase 1: warp counts -> per-warp exclusive base (once) ----
    int blockBase = b * CHUNK;
    int warpBase  = blockBase + warp * 1024;
    bool full = (blockBase + CHUNK <= n);
    const unsigned* g_words = reinterpret_cast<const unsigned*>(g_mask4);
    unsigned myword = g_words[(blockBase >> 5) + warp * 32 + lane];
    int wtot = __popc(myword);
#pragma unroll
    for (int o = 16; o; o >>= 1) wtot += __shfl_xor_sync(0xffffffffu, wtot, o);
    __shared__ int s_wc[NWARPS];
    if (lane == 0) s_wc[warp] = wtot;
    __syncthreads();
#pragma unroll
    for (int i = 0; i < NWARPS; ++i)
        if (i < warp) kwarp += s_wc[i];

    // ---- phase 2: full-unrolled pipelined tiles ----
    const unsigned lt  = (1u << lane) - 1u;
    const int      Pp1 = P + 1;
    float acc = 0.0f;

    // preload tile 0
    float4 pv;
    uint4  mw = g_mask4[warpBase >> 7];
    if (full) {
        pv = *reinterpret_cast<const float4*>(predict + warpBase + lane * 4);
    } else {
        int i0 = warpBase + lane * 4;
        pv.x = (i0 + 0 < n) ? predict[i0 + 0] : 0.0f;
        pv.y = (i0 + 1 < n) ? predict[i0 + 1] : 0.0f;
        pv.z = (i0 + 2 < n) ? predict[i0 + 2] : 0.0f;
        pv.w = (i0 + 3 < n) ? predict[i0 + 3] : 0.0f;
    }

#pragma unroll
    for (int j = 0; j < 8; ++j) {
        float4 pv_n;
        uint4  mw_n;
        if (j < 7) {                      // static under full unroll
            int tb = warpBase + (j + 1) * 128;
            mw_n = g_mask4[tb >> 7];
            if (full) {
                pv_n = *reinterpret_cast<const float4*>(predict + tb + lane * 4);
            } else {
                int i0 = tb + lane * 4;
                pv_n.x = (i0 + 0 < n) ? predict[i0 + 0] : 0.0f;
                pv_n.y = (i0 + 1 < n) ? predict[i0 + 1] : 0.0f;
                pv_n.z = (i0 + 2 < n) ? predict[i0 + 2] : 0.0f;
                pv_n.w = (i0 + 3 < n) ? predict[i0 + 3] : 0.0f;
            }
        }

        int iA   = warpBase + j * 128 + lane * 4;
        int pre4 = __popc(mw.x & lt) + __popc(mw.y & lt)
                 + __popc(mw.z & lt) + __popc(mw.w & lt);
        int b0 = (mw.x >> lane) & 1;
        int b1 = (mw.y >> lane) & 1;
        int b2 = (mw.z >> lane) & 1;
        int b3 = (mw.w >> lane) & 1;

        int kexc = kwarp + pre4;          // exclusive before this thread
        int kp1  = kexc + 1;
        int dn   = Pp1 + iA - kexc;

        kp1 += b0; dn += 1 - b0;
        { float u = uterm(pv.x, b0, kp1, dn, s2); acc = fmaf(u, u, acc); }
        kp1 += b1; dn += 1 - b1;
        { float u = uterm(pv.y, b1, kp1, dn, s2); acc = fmaf(u, u, acc); }
        kp1 += b2; dn += 1 - b2;
        { float u = uterm(pv.z, b2, kp1, dn, s2); acc = fmaf(u, u, acc); }
        kp1 += b3; dn += 1 - b3;
        { float u = uterm(pv.w, b3, kp1, dn, s2); acc = fmaf(u, u, acc); }

        // lane31's kp1 == kwarp + tile_count + 1  -> advance warp base
        kwarp = __shfl_sync(0xffffffffu, kp1, 31) - 1;
        pv = pv_n;
        mw = mw_n;
    }

    // ---- block reduce -> g_partial ----
#pragma unroll
    for (int o = 16; o; o >>= 1) acc += __shfl_xor_sync(0xffffffffu, acc, o);
    __shared__ float s_acc[NWARPS];
    if (lane == 0) s_acc[warp] = acc;
    __syncthreads();

    __shared__ unsigned s_ticket;
    if (tid == 0) {
        float s = 0.0f;
#pragma unroll
        for (int i = 0; i < NWARPS; ++i) s += s_acc[i];
        g_partial[b] = s;
        __threadfence();
        s_ticket = atomicAdd(&g_cnt2, 1u);
    }
    __syncthreads();

    // ---- last block: fixed-order double reduce, scale by inv^2 -> out ----
    if (s_ticket == (unsigned)(nb - 1)) {
        __threadfence();
        double s = 0.0;
        for (int i = tid; i < nb; i += NTHREADS) s += (double)g_partial[i];
#pragma unroll
        for (int o = 16; o; o >>= 1) s += __shfl_down_sync(0xffffffffu, s, o);
        __shared__ double sd[NWARPS];
        if (lane == 0) sd[warp] = s;
        __syncthreads();
        if (tid == 0) {
            double t = 0.0;
#pragma unroll
            for (int i = 0; i < NWARPS; ++i) t += sd[i];
            float inv = 1.0f / sum_s;      // inv_sum_s
            out[0] = (float)(t * (double)(inv * inv));
            g_cnt2 = 0;
        }
    }
}

extern "C" void kernel_launch(void* const* d_in, const int* in_sizes, int n_in,
                              void* d_out, int out_size) {
    const float* predict = (const float*)d_in[0];
    const float* score   = (const float*)d_in[1];
    int n  = in_sizes[0];
    int nb = (n + CHUNK - 1) / CHUNK;
    if (nb > MAX_BLOCKS) nb = MAX_BLOCKS;

    k_count<<<nb, NTHREADS>>>(score, n, nb);
    k_main <<<nb, NTHREADS>>>(predict, (float*)d_out, n, nb);
}